// round 15
// baseline (speedup 1.0000x reference)
#include <cuda_runtime.h>
#include <cuda_fp16.h>
#include <cstdint>

#define BATCH 8
#define NNODE 4096
#define DIM   256
#define TOPK  8
#define NGRP  144                // sum over it of ceil((32-it)/4)

static __device__ __forceinline__ float neg_inf() { return __int_as_float(0xff800000); }

// ---------------- device scratch ----------------
__device__ __half g_Xhi[BATCH * NNODE * DIM];
__device__ float  g_Xn [BATCH * NNODE * DIM];             // normalized fp32
__device__ float  g_cv[(size_t)BATCH * NNODE * 32 * 8];   // per-row per-slot hi candidates
__device__ int    g_ci[(size_t)BATCH * NNODE * 32 * 8];
__device__ int    g_topk[BATCH * NNODE * TOPK];
__device__ float  g_Wt[DIM * DIM];

// ---------------- helpers ----------------
__device__ __forceinline__ uint32_t smem_to_u32(const void* p) {
    uint32_t a;
    asm("{ .reg .u64 t; cvta.to.shared.u64 t, %1; cvt.u32.u64 %0, t; }" : "=r"(a) : "l"(p));
    return a;
}

#define CP_ASYNC16(dst, src) \
    asm volatile("cp.async.cg.shared.global [%0], [%1], 16;" :: "r"((uint32_t)(dst)), "l"(src) : "memory")
#define CP_ASYNC_COMMIT() asm volatile("cp.async.commit_group;" ::: "memory")
#define CP_ASYNC_WAIT0()  asm volatile("cp.async.wait_group 0;" ::: "memory")

#define LDSM_X4(R0, R1, R2, R3, ADDR) \
    asm volatile("ldmatrix.sync.aligned.m8n8.x4.shared.b16 {%0,%1,%2,%3}, [%4];" \
                 : "=r"(R0), "=r"(R1), "=r"(R2), "=r"(R3) : "r"((uint32_t)(ADDR)))

#define MMA16816(C, A, B0, B1) \
    asm volatile("mma.sync.aligned.m16n8k16.row.col.f32.f16.f16.f32 " \
                 "{%0,%1,%2,%3}, {%4,%5,%6,%7}, {%8,%9}, {%0,%1,%2,%3};" \
                 : "+f"((C)[0]), "+f"((C)[1]), "+f"((C)[2]), "+f"((C)[3]) \
                 : "r"((A)[0]), "r"((A)[1]), "r"((A)[2]), "r"((A)[3]), "r"(B0), "r"(B1))

// insert (v, idx) into sorted-desc top-8 (strict >, earlier index wins ties)
#define TOP8_INSERT(bv, bi, th, v, idx) do {                                   \
    if ((v) > (bv)[7]) {                                                       \
        (bv)[7] = (v); (bi)[7] = (idx);                                        \
        _Pragma("unroll")                                                      \
        for (int _k = 7; _k >= 1; _k--) {                                      \
            const bool _sw = (bv)[_k] > (bv)[_k - 1];                          \
            const float _xv = (bv)[_k]; const int _xi = (bi)[_k];              \
            (bv)[_k]     = _sw ? (bv)[_k - 1] : (bv)[_k];                      \
            (bi)[_k]     = _sw ? (bi)[_k - 1] : (bi)[_k];                      \
            (bv)[_k - 1] = _sw ? _xv : (bv)[_k - 1];                           \
            (bi)[_k - 1] = _sw ? _xi : (bi)[_k - 1];                           \
        }                                                                      \
        (th) = __float2half_rn((bv)[7]);                                       \
    }                                                                          \
} while (0)

// ---------------------------------------------------------------------------
// Kernel 1: L2-normalize rows -> fp32 g_Xn + f16 g_Xhi
// ---------------------------------------------------------------------------
__global__ void k_norm_split(const float* __restrict__ X) {
    const int gr = blockIdx.x * 8 + (threadIdx.x >> 5);
    const int lane = threadIdx.x & 31;
    const float4* p = (const float4*)(X + (size_t)gr * DIM);
    float4 v0 = p[lane * 2], v1 = p[lane * 2 + 1];
    float ss = v0.x*v0.x + v0.y*v0.y + v0.z*v0.z + v0.w*v0.w
             + v1.x*v1.x + v1.y*v1.y + v1.z*v1.z + v1.w*v1.w;
    #pragma unroll
    for (int off = 16; off >= 1; off >>= 1) ss += __shfl_xor_sync(0xFFFFFFFFu, ss, off);
    const float inv = 1.0f / fmaxf(sqrtf(ss), 1e-12f);
    float v[8] = {v0.x*inv, v0.y*inv, v0.z*inv, v0.w*inv, v1.x*inv, v1.y*inv, v1.z*inv, v1.w*inv};
    uint32_t hp[4];
    #pragma unroll
    for (int k = 0; k < 4; k++) {
        __half2 hh = __halves2half2(__float2half_rn(v[2*k]), __float2half_rn(v[2*k+1]));
        hp[k] = *(uint32_t*)&hh;
    }
    const size_t o = (size_t)gr * DIM + lane * 8;
    *(uint4*)(g_Xhi + o) = make_uint4(hp[0], hp[1], hp[2], hp[3]);
    *(float4*)(g_Xn + o)     = make_float4(v[0], v[1], v[2], v[3]);
    *(float4*)(g_Xn + o + 4) = make_float4(v[4], v[5], v[6], v[7]);
}

// ---------------------------------------------------------------------------
// Kernel 1b: transpose W
// ---------------------------------------------------------------------------
__global__ void k_wt(const float* __restrict__ W) {
    __shared__ float s[32][33];
    const int e0 = blockIdx.x * 32, d0 = blockIdx.y * 32;
    const int tx = threadIdx.x, ty = threadIdx.y;
    for (int i = ty; i < 32; i += 8) s[i][tx] = W[(e0 + i) * DIM + d0 + tx];
    __syncthreads();
    for (int i = ty; i < 32; i += 8) g_Wt[(d0 + i) * DIM + e0 + tx] = s[tx][i];
}

// ---------------------------------------------------------------------------
// Kernel 1c: no-op pad (keeps k_sim_topk as the 4th launch for ncu)
// ---------------------------------------------------------------------------
__global__ void k_pad() {}

// ---------------------------------------------------------------------------
// Kernel 2: hi-only sim, 256 threads, 2 CTAs/SM (smem 100KB).
//   Per tile: [load B chunk -> MMA] x2 serial in one B buffer, spill D (f16,
//   stride 136 halves = B stride) into the B buffer, then gated scans:
//   row scan uint4 (8 values) with f16 hmax gating; col scan f16-gated.
// ---------------------------------------------------------------------------
#define SA 264
#define A_BYTES (128 * SA * 2)            // 67584
#define B_BYTES (128 * 136 * 2)           // 34816
#define DS2 136                           // f16 D stride (row base 272B, 16B-aligned)
#define OFF_AHI 0
#define OFF_B   A_BYTES                   // B buffer; D overlays it exactly
#define K2_SMEM (A_BYTES + B_BYTES)       // 102400 -> 2 CTAs/SM

__global__ __launch_bounds__(256, 2) void k_sim_topk() {
    extern __shared__ char smem[];
    const uint32_t sb = smem_to_u32(smem);
    const int t = threadIdx.x, lane = t & 31, wid = t >> 5;
    const int b = blockIdx.y;

    int g = blockIdx.x, it = 0;
    while (true) { const int ng = (32 - it + 3) >> 2; if (g < ng) break; g -= ng; it++; }
    const int jt0 = it + g * 4;
    const int jt1 = (jt0 + 4 < 32) ? jt0 + 4 : 32;
    const int i0 = it * 128;
    const int wm = wid >> 1, wn = wid & 1;

    // ---- A (hi) -> smem ----
    {
        const __half* srch = g_Xhi + ((size_t)(b * NNODE) + i0) * DIM;
        #pragma unroll
        for (int s = 0; s < 16; s++) {
            const int p = t + 256 * s;          // 4096 pieces of 16B
            const int row = p >> 5, pc = p & 31;
            CP_ASYNC16(sb + OFF_AHI + row * 528 + pc * 16, srch + (size_t)row * DIM + pc * 8);
        }
    }

    auto loadB = [&](int jt, int chunk) {
        const __half* src = g_Xhi + ((size_t)(b * NNODE) + jt * 128) * DIM + chunk * 128;
        #pragma unroll
        for (int s = 0; s < 8; s++) {
            const int p = t + 256 * s;          // 2048 pieces
            const int row = p >> 4, pc = p & 15;
            CP_ASYNC16(sb + OFF_B + row * 272 + pc * 16, src + (size_t)row * DIM + pc * 8);
        }
    };

    const uint32_t aRowB = (uint32_t)(wm * 32 + (lane & 15)) * 528 + ((lane >> 4) << 4);
    const uint32_t bRowB = (uint32_t)((lane & 7) + ((lane >> 4) << 3) + wn * 64) * 272
                         + ((lane & 8) ? 16 : 0);

    float acc[2][8][4];
    #pragma unroll
    for (int mf = 0; mf < 2; mf++)
        #pragma unroll
        for (int nn = 0; nn < 8; nn++)
            #pragma unroll
            for (int c = 0; c < 4; c++) acc[mf][nn][c] = 0.0f;

    for (int jt = jt0; jt < jt1; jt++) {
        const int j0 = jt * 128;

        #pragma unroll
        for (int st = 0; st < 2; st++) {
            loadB(jt, st);
            CP_ASYNC_COMMIT();
            CP_ASYNC_WAIT0();
            __syncthreads();                    // B(st) visible; prior readers done

            const int kbyte0 = st * 256;
            #pragma unroll
            for (int k16 = 0; k16 < 8; k16++) {
                uint32_t Bf[4][4];
                const uint32_t bk = sb + OFF_B + bRowB + k16 * 32;
                #pragma unroll
                for (int nf = 0; nf < 4; nf++)
                    LDSM_X4(Bf[nf][0], Bf[nf][1], Bf[nf][2], Bf[nf][3], bk + nf * (16 * 272));
                const uint32_t akb = aRowB + kbyte0 + k16 * 32;
                uint32_t Af[2][4];
                #pragma unroll
                for (int mf = 0; mf < 2; mf++)
                    LDSM_X4(Af[mf][0], Af[mf][1], Af[mf][2], Af[mf][3],
                            sb + OFF_AHI + akb + mf * (16 * 528));
                #pragma unroll
                for (int mf = 0; mf < 2; mf++)
                    #pragma unroll
                    for (int nf = 0; nf < 4; nf++) {
                        MMA16816(acc[mf][nf * 2],     Af[mf], Bf[nf][0], Bf[nf][1]);
                        MMA16816(acc[mf][nf * 2 + 1], Af[mf], Bf[nf][2], Bf[nf][3]);
                    }
            }
            __syncthreads();                    // all B(st) reads done before overwrite
        }

        // ---- spill D (f16) into the B buffer, reset acc ----
        __half* Dh = (__half*)(smem + OFF_B);
        #pragma unroll
        for (int mf = 0; mf < 2; mf++)
            #pragma unroll
            for (int h = 0; h < 2; h++) {
                const int row = wm * 32 + mf * 16 + h * 8 + (lane >> 2);
                #pragma unroll
                for (int nn = 0; nn < 8; nn++) {
                    const int col = wn * 64 + nn * 8 + (lane & 3) * 2;
                    *(__half2*)(Dh + row * DS2 + col) =
                        __floats2half2_rn(acc[mf][nn][h * 2], acc[mf][nn][h * 2 + 1]);
                }
            }
        #pragma unroll
        for (int mf = 0; mf < 2; mf++)
            #pragma unroll
            for (int nn = 0; nn < 8; nn++)
                #pragma unroll
                for (int c = 0; c < 4; c++) acc[mf][nn][c] = 0.0f;
        __syncthreads();

        // ---- gated scans ----
        if (t < 128) {
            // row scan: 16 x uint4 (8 values), f16 hmax gate
            const uint4* rp = (const uint4*)((const char*)Dh + (size_t)t * (DS2 * 2));
            float bv[8]; int bi[8];
            #pragma unroll
            for (int k = 0; k < 8; k++) { bv[k] = neg_inf(); bi[k] = 0x7FFFFFFF; }
            __half th = __float2half_rn(neg_inf());
            #pragma unroll 4
            for (int i = 0; i < 16; i++) {
                const uint4 u = rp[i];
                const __half2 h0 = *(const __half2*)&u.x, h1 = *(const __half2*)&u.y;
                const __half2 h2 = *(const __half2*)&u.z, h3 = *(const __half2*)&u.w;
                const __half2 mm = __hmax2(__hmax2(h0, h1), __hmax2(h2, h3));
                const __half mx = __hmax(__low2half(mm), __high2half(mm));
                if (__hgt(mx, th)) {
                    const float2 f0 = __half22float2(h0), f1 = __half22float2(h1);
                    const float2 f2 = __half22float2(h2), f3 = __half22float2(h3);
                    const float vals[8] = {f0.x, f0.y, f1.x, f1.y, f2.x, f2.y, f3.x, f3.y};
                    #pragma unroll
                    for (int u8 = 0; u8 < 8; u8++)
                        TOP8_INSERT(bv, bi, th, vals[u8], j0 + i * 8 + u8);
                }
            }
            const size_t base = (((size_t)(b * NNODE) + i0 + t) * 32 + jt) * 8;
            #pragma unroll
            for (int k = 0; k < 8; k++) { g_cv[base + k] = bv[k]; g_ci[base + k] = bi[k]; }
        } else if (it != jt) {
            // col scan: f16-gated scalar
            const int c = t - 128;
            const __half* cp = Dh + c;
            float bv[8]; int bi[8];
            #pragma unroll
            for (int k = 0; k < 8; k++) { bv[k] = neg_inf(); bi[k] = 0x7FFFFFFF; }
            __half th = __float2half_rn(neg_inf());
            #pragma unroll 4
            for (int s = 0; s < 128; s++) {
                const __half hv = cp[(size_t)s * DS2];
                if (__hgt(hv, th)) {
                    const float v = __half2float(hv);
                    TOP8_INSERT(bv, bi, th, v, i0 + s);
                }
            }
            const size_t base = (((size_t)(b * NNODE) + j0 + c) * 32 + it) * 8;
            #pragma unroll
            for (int k = 0; k < 8; k++) { g_cv[base + k] = bv[k]; g_ci[base + k] = bi[k]; }
        }
        __syncthreads();                        // scans done before next tile's B load
    }
}

// ---------------------------------------------------------------------------
// Kernel 2b: merge 32x8 hi-lists -> top-16 candidates -> exact fp32 refine
// ---------------------------------------------------------------------------
__global__ __launch_bounds__(256) void k_merge_refine() {
    const int row  = (blockIdx.x * 256 + threadIdx.x) >> 5;   // 0..B*N-1
    const int lane = threadIdx.x & 31;
    const size_t base = ((size_t)row * 32 + lane) * 8;
    float v[8]; int ix[8];
    {
        const float4 a = *(const float4*)(g_cv + base);
        const float4 c = *(const float4*)(g_cv + base + 4);
        const int4 ia = *(const int4*)(g_ci + base);
        const int4 ic = *(const int4*)(g_ci + base + 4);
        v[0]=a.x; v[1]=a.y; v[2]=a.z; v[3]=a.w; v[4]=c.x; v[5]=c.y; v[6]=c.z; v[7]=c.w;
        ix[0]=ia.x; ix[1]=ia.y; ix[2]=ia.z; ix[3]=ia.w; ix[4]=ic.x; ix[5]=ic.y; ix[6]=ic.z; ix[7]=ic.w;
    }
    int cand = 0x7FFFFFFF;
    #pragma unroll
    for (int s = 0; s < 16; s++) {
        const float cv_ = v[0]; const int ci_ = ix[0];
        float rv = cv_; int ri = ci_;
        #pragma unroll
        for (int off = 16; off >= 1; off >>= 1) {
            const float ov = __shfl_xor_sync(0xFFFFFFFFu, rv, off);
            const int   oi = __shfl_xor_sync(0xFFFFFFFFu, ri, off);
            if (ov > rv || (ov == rv && oi < ri)) { rv = ov; ri = oi; }
        }
        const bool adv = (ri == ci_) && (rv == cv_);
        #pragma unroll
        for (int k = 0; k < 7; k++) {
            v[k]  = adv ? v[k + 1]  : v[k];
            ix[k] = adv ? ix[k + 1] : ix[k];
        }
        if (adv) { v[7] = neg_inf(); ix[7] = 0x7FFFFFFF; }
        if (s == lane) cand = ri;
    }

    // ---- exact fp32 refinement of the 16 candidates ----
    const float* Xb  = g_Xn + ((size_t)(row >> 12) * NNODE) * DIM;   // batch base
    const float* own = g_Xn + (size_t)row * DIM;
    const float4 a0 = ((const float4*)own)[lane * 2];
    const float4 a1 = ((const float4*)own)[lane * 2 + 1];
    float myv = neg_inf();
    #pragma unroll
    for (int c = 0; c < 16; c++) {
        const int jc = __shfl_sync(0xFFFFFFFFu, cand, c);
        const float4* cr = (const float4*)(Xb + (size_t)jc * DIM);
        const float4 c0 = cr[lane * 2], c1 = cr[lane * 2 + 1];
        float p = a0.x*c0.x + a0.y*c0.y + a0.z*c0.z + a0.w*c0.w
                + a1.x*c1.x + a1.y*c1.y + a1.z*c1.z + a1.w*c1.w;
        #pragma unroll
        for (int off = 16; off >= 1; off >>= 1) p += __shfl_xor_sync(0xFFFFFFFFu, p, off);
        if (lane == c) myv = p;
    }
    int out = 0;
    #pragma unroll
    for (int k = 0; k < 8; k++) {
        float rv = myv; int ri = cand;
        #pragma unroll
        for (int off = 16; off >= 1; off >>= 1) {
            const float ov = __shfl_xor_sync(0xFFFFFFFFu, rv, off);
            const int   oi = __shfl_xor_sync(0xFFFFFFFFu, ri, off);
            if (ov > rv || (ov == rv && oi < ri)) { rv = ov; ri = oi; }
        }
        if (ri == cand) myv = neg_inf();    // unique index -> unique owner
        if (k == lane) out = ri;
    }
    if (lane < 8) g_topk[row * TOPK + lane] = out;
}

// ---------------------------------------------------------------------------
// Kernel 3: gather-mean -> GEMM(W^T) -> +bias +residual -> LayerNorm
// ---------------------------------------------------------------------------
#define K3_SMEM ((2 * 32 * 260) * 4 + 256 * 4)

__global__ __launch_bounds__(256, 2) void k_msg_gemm_ln(
    const float* __restrict__ X, const float* __restrict__ bias,
    const float* __restrict__ gamma, const float* __restrict__ beta,
    float* __restrict__ outp)
{
    extern __shared__ float smemf[];
    float* msg = smemf;
    float* Ws  = msg + 32 * 260;
    int* sidx  = (int*)(Ws + 32 * 260);

    const int b = blockIdx.y, n0 = blockIdx.x * 32;
    const int t = threadIdx.x, w = t >> 5, lane = t & 31;
    const float* Xb = X + b * (NNODE * DIM);

    sidx[t] = g_topk[(b * NNODE + n0) * TOPK + t];
    __syncthreads();

    for (int rr = 0; rr < 4; rr++) {
        const int r = w * 4 + rr;
        float4 a0 = make_float4(0,0,0,0), a1 = make_float4(0,0,0,0);
        #pragma unroll
        for (int nb = 0; nb < 8; nb++) {
            const int j = sidx[r * 8 + nb];
            const float4* src = (const float4*)(Xb + j * DIM);
            const float4 v0 = src[lane], v1 = src[lane + 32];
            a0.x += v0.x; a0.y += v0.y; a0.z += v0.z; a0.w += v0.w;
            a1.x += v1.x; a1.y += v1.y; a1.z += v1.z; a1.w += v1.w;
        }
        const float sc = 0.125f;
        a0.x *= sc; a0.y *= sc; a0.z *= sc; a0.w *= sc;
        a1.x *= sc; a1.y *= sc; a1.z *= sc; a1.w *= sc;
        *(float4*)(msg + r * 260 + lane * 4)       = a0;
        *(float4*)(msg + r * 260 + 128 + lane * 4) = a1;
    }

    const int tx = t & 31, ty = t >> 5;          // 8 row-groups of 4 rows
    const int r0 = ty * 4;
    float acc[4][8];
    #pragma unroll
    for (int i = 0; i < 4; i++)
        #pragma unroll
        for (int jq = 0; jq < 8; jq++) acc[i][jq] = 0.0f;

    for (int kc = 0; kc < DIM; kc += 32) {
        __syncthreads();
        #pragma unroll
        for (int s = 0; s < 8; s++) {
            const int lin = t + 256 * s;
            const int e4 = (lin & 63) * 4;
            const int dd = lin >> 6;
            *(float4*)(Ws + dd * 260 + e4) = *(const float4*)(g_Wt + (kc + dd) * DIM + e4);
        }
        __syncthreads();
        #pragma unroll 4
        for (int kk = 0; kk < 32; kk++) {
            const float4 w0 = *(const float4*)(Ws + kk * 260 + tx * 8);
            const float4 w1 = *(const float4*)(Ws + kk * 260 + tx * 8 + 4);
            #pragma unroll
            for (int i = 0; i < 4; i++) {
                const float m = msg[(r0 + i) * 260 + kc + kk];
                acc[i][0] = fmaf(m, w0.x, acc[i][0]);
                acc[i][1] = fmaf(m, w0.y, acc[i][1]);
                acc[i][2] = fmaf(m, w0.z, acc[i][2]);
                acc[i][3] = fmaf(m, w0.w, acc[i][3]);
                acc[i][4] = fmaf(m, w1.x, acc[i][4]);
                acc[i][5] = fmaf(m, w1.y, acc[i][5]);
                acc[i][6] = fmaf(m, w1.z, acc[i][6]);
                acc[i][7] = fmaf(m, w1.w, acc[i][7]);
            }
        }
    }

    const int e = tx * 8;
    const float4 bb0 = *(const float4*)(bias + e);
    const float4 bb1 = *(const float4*)(bias + e + 4);
    float z[4][8];
    #pragma unroll
    for (int i = 0; i < 4; i++) {
        const float4 x0 = *(const float4*)(Xb + (size_t)(n0 + r0 + i) * DIM + e);
        const float4 x1 = *(const float4*)(Xb + (size_t)(n0 + r0 + i) * DIM + e + 4);
        z[i][0] = acc[i][0] + bb0.x + x0.x;  z[i][1] = acc[i][1] + bb0.y + x0.y;
        z[i][2] = acc[i][2] + bb0.z + x0.z;  z[i][3] = acc[i][3] + bb0.w + x0.w;
        z[i][4] = acc[i][4] + bb1.x + x1.x;  z[i][5] = acc[i][5] + bb1.y + x1.y;
        z[i][6] = acc[i][6] + bb1.z + x1.z;  z[i][7] = acc[i][7] + bb1.w + x1.w;
    }
    float mu[4], is[4];
    #pragma unroll
    for (int i = 0; i < 4; i++) {
        float s0 = 0.0f;
        #pragma unroll
        for (int jq = 0; jq < 8; jq++) s0 += z[i][jq];
        #pragma unroll
        for (int off = 16; off >= 1; off >>= 1) s0 += __shfl_xor_sync(0xFFFFFFFFu, s0, off);
        mu[i] = s0 * (1.0f / 256.0f);
    }
    #pragma unroll
    for (int i = 0; i < 4; i++) {
        float q0 = 0.0f;
        #pragma unroll
        for (int jq = 0; jq < 8; jq++) { const float d = z[i][jq] - mu[i]; q0 += d * d; }
        #pragma unroll
        for (int off = 16; off >= 1; off >>= 1) q0 += __shfl_xor_sync(0xFFFFFFFFu, q0, off);
        is[i] = rsqrtf(q0 * (1.0f / 256.0f) + 1e-5f);
    }
    const float4 g0 = *(const float4*)(gamma + e);
    const float4 g1 = *(const float4*)(gamma + e + 4);
    const float4 be0 = *(const float4*)(beta + e);
    const float4 be1 = *(const float4*)(beta + e + 4);
    #pragma unroll
    for (int i = 0; i < 4; i++) {
        float4 o0, o1;
        o0.x = (z[i][0] - mu[i]) * is[i] * g0.x + be0.x;
        o0.y = (z[i][1] - mu[i]) * is[i] * g0.y + be0.y;
        o0.z = (z[i][2] - mu[i]) * is[i] * g0.z + be0.z;
        o0.w = (z[i][3] - mu[i]) * is[i] * g0.w + be0.w;
        o1.x = (z[i][4] - mu[i]) * is[i] * g1.x + be1.x;
        o1.y = (z[i][5] - mu[i]) * is[i] * g1.y + be1.y;
        o1.z = (z[i][6] - mu[i]) * is[i] * g1.z + be1.z;
        o1.w = (z[i][7] - mu[i]) * is[i] * g1.w + be1.w;
        float* op = outp + (size_t)(b * NNODE + n0 + r0 + i) * DIM + e;
        *(float4*)op = o0;
        *(float4*)(op + 4) = o1;
    }
}

// ---------------------------------------------------------------------------
extern "C" void kernel_launch(void* const* d_in, const int* in_sizes, int n_in,
                              void* d_out, int out_size) {
    const float* X     = (const float*)d_in[0];
    const float* W     = (const float*)d_in[1];
    const float* bias  = (const float*)d_in[2];
    const float* gamma = (const float*)d_in[3];
    const float* beta  = (const float*)d_in[4];
    float* outp = (float*)d_out;

    static bool s_attr = false;
    if (!s_attr) {
        cudaFuncSetAttribute(k_sim_topk, cudaFuncAttributeMaxDynamicSharedMemorySize, K2_SMEM);
        cudaFuncSetAttribute(k_msg_gemm_ln, cudaFuncAttributeMaxDynamicSharedMemorySize, K3_SMEM);
        s_attr = true;
    }

    k_norm_split<<<BATCH * NNODE / 8, 256>>>(X);           // launch 1
    k_wt<<<dim3(DIM / 32, DIM / 32), dim3(32, 8)>>>(W);    // launch 2
    k_pad<<<1, 32>>>();                                    // launch 3 (pad)
    k_sim_topk<<<dim3(NGRP, BATCH), 256, K2_SMEM>>>();     // launch 4 (profiled)
    k_merge_refine<<<BATCH * NNODE * 32 / 256, 256>>>();   // launch 5
    k_msg_gemm_ln<<<dim3(NNODE / 32, BATCH), 256, K3_SMEM>>>(X, bias, gamma, beta, outp);
}